// round 6
// baseline (speedup 1.0000x reference)
#include <cuda_runtime.h>

#define NE 1200000
#define NN 50000
#define DF 64
#define HID 32

__device__ int g_idx_is64;

// Full weight matrices in constant memory; the kernel reads only columns
// 0..15 of each row through the LDC port. Columns 16..31 are staged into
// shared memory (L1tex port). The two ports run in parallel, and each stays
// below the FMA-pipe cost of the FFMA2s it feeds.
__constant__ float cW1[2 * DF * HID];   // 16 KB (constant half: cols 0..15)
__constant__ float cW2[HID * HID];      // 4 KB
__constant__ float cb1[HID];
__constant__ float cb2[HID];
__constant__ float cW3[HID];
__constant__ float cb3[1];

// ---- packed f32x2 helpers (Blackwell sm_103a) ----
__device__ __forceinline__ unsigned long long pk2(float a, float b) {
    unsigned long long r;
    asm("mov.b64 %0, {%1, %2};" : "=l"(r) : "f"(a), "f"(b));
    return r;
}
__device__ __forceinline__ void upk2(unsigned long long v, float& a, float& b) {
    asm("mov.b64 {%0, %1}, %2;" : "=f"(a), "=f"(b) : "l"(v));
}
__device__ __forceinline__ unsigned long long fma2(unsigned long long a,
                                                   unsigned long long b,
                                                   unsigned long long c) {
    unsigned long long d;
    asm("fma.rn.f32x2 %0, %1, %2, %3;" : "=l"(d) : "l"(a), "l"(b), "l"(c));
    return d;
}

// Fused: zero output + detect edge_index dtype (JAX canonicalizes int64->int32
// unless x64 mode). Genuine int64 has every 8-byte value in [0, NN).
__global__ void init_kernel(const long long* __restrict__ ei,
                            float* __restrict__ out) {
    int i = blockIdx.x * blockDim.x + threadIdx.x;
    if (i < NN) out[i] = 0.0f;
    if (i == 0) {
        int ok64 = 1;
        for (int k = 0; k < 8; k++) {
            long long v = ei[k];
            if (v < 0 || v >= NN) ok64 = 0;
        }
        g_idx_is64 = ok64;
    }
}

__global__ __launch_bounds__(256, 2)
void edge_mlp_kernel(const float4* __restrict__ x4,
                     const void* __restrict__ ei_raw,
                     const float* __restrict__ u,
                     const float* __restrict__ W1g,
                     const float* __restrict__ W2g,
                     float* __restrict__ out)
{
    // smem halves: columns 16..31 of each W row
    __shared__ __align__(16) float sW1[2 * DF * 16];   // 8 KB
    __shared__ __align__(16) float sW2[HID * 16];      // 2 KB

    for (int i = threadIdx.x; i < 2 * DF * 16 / 4; i += blockDim.x) {
        int k = i >> 2, p = i & 3;
        ((float4*)sW1)[i] = ((const float4*)W1g)[k * 8 + 4 + p];
    }
    for (int i = threadIdx.x; i < HID * 16 / 4; i += blockDim.x) {
        int k = i >> 2, p = i & 3;
        ((float4*)sW2)[i] = ((const float4*)W2g)[k * 8 + 4 + p];
    }
    __syncthreads();

    long e0 = (long)blockIdx.x * 512 + threadIdx.x;
    long e1 = e0 + 256;
    if (e0 >= NE) return;
    bool v1 = (e1 < NE);
    if (!v1) e1 = e0;   // duplicate work, atomic suppressed below

    int row0, col0, row1, col1;
    if (g_idx_is64) {
        const long long* ei = (const long long*)ei_raw;
        row0 = (int)ei[e0];      row1 = (int)ei[e1];
        col0 = (int)ei[NE + e0]; col1 = (int)ei[NE + e1];
    } else {
        const int* ei = (const int*)ei_raw;
        row0 = ei[e0];      row1 = ei[e1];
        col0 = ei[NE + e0]; col1 = ei[NE + e1];
    }
    row0 = min(max(row0, 0), NN - 1); col0 = min(max(col0, 0), NN - 1);
    row1 = min(max(row1, 0), NN - 1); col1 = min(max(col1, 0), NN - 1);

    // ---- layer 1 for BOTH edges ----
    // h[0..7]  <- output cols 0..15  (constant port)
    // h[8..15] <- output cols 16..31 (shared port)
    // Net mapping: h[j] holds cols (2j, 2j+1) for ALL j, matching b1 layout.
    unsigned long long h0[16], h1[16];
    const unsigned long long* b1p = (const unsigned long long*)cb1;
    #pragma unroll
    for (int j = 0; j < 16; j++) { h0[j] = b1p[j]; h1[j] = b1p[j]; }

    #pragma unroll 1
    for (int half = 0; half < 2; half++) {
        int n0 = half ? col0 : row0;
        int n1 = half ? col1 : row1;
        const float4* xp0 = x4 + (long)n0 * (DF / 4);
        const float4* xp1 = x4 + (long)n1 * (DF / 4);
        #pragma unroll 2
        for (int q = 0; q < DF / 4; q++) {
            float4 a = __ldg(xp0 + q);
            float4 b = __ldg(xp1 + q);
            float av[4] = {a.x, a.y, a.z, a.w};
            float bv[4] = {b.x, b.y, b.z, b.w};
            #pragma unroll
            for (int c = 0; c < 4; c++) {
                unsigned long long xx0 = pk2(av[c], av[c]);
                unsigned long long xx1 = pk2(bv[c], bv[c]);
                int k = half * DF + q * 4 + c;
                const ulonglong2* wc = (const ulonglong2*)(cW1 + k * 32);
                const ulonglong2* ws = (const ulonglong2*)(sW1 + k * 16);
                ulonglong2 c0 = wc[0], c1 = wc[1];   // LDC.128 x2 (cols 0..7)
                ulonglong2 s0 = ws[0], s1 = ws[1];   // LDS.128 x2 (cols 16..23)
                h0[0] = fma2(xx0, c0.x, h0[0]);  h0[1] = fma2(xx0, c0.y, h0[1]);
                h0[2] = fma2(xx0, c1.x, h0[2]);  h0[3] = fma2(xx0, c1.y, h0[3]);
                h1[0] = fma2(xx1, c0.x, h1[0]);  h1[1] = fma2(xx1, c0.y, h1[1]);
                h1[2] = fma2(xx1, c1.x, h1[2]);  h1[3] = fma2(xx1, c1.y, h1[3]);
                h0[8]  = fma2(xx0, s0.x, h0[8]);  h0[9]  = fma2(xx0, s0.y, h0[9]);
                h0[10] = fma2(xx0, s1.x, h0[10]); h0[11] = fma2(xx0, s1.y, h0[11]);
                h1[8]  = fma2(xx1, s0.x, h1[8]);  h1[9]  = fma2(xx1, s0.y, h1[9]);
                h1[10] = fma2(xx1, s1.x, h1[10]); h1[11] = fma2(xx1, s1.y, h1[11]);
                ulonglong2 c2 = wc[2];               // LDC.128 (cols 8..11)
                ulonglong2 s2 = ws[2];               // LDS.128 (cols 24..27)
                h0[4] = fma2(xx0, c2.x, h0[4]);  h0[5] = fma2(xx0, c2.y, h0[5]);
                h1[4] = fma2(xx1, c2.x, h1[4]);  h1[5] = fma2(xx1, c2.y, h1[5]);
                h0[12] = fma2(xx0, s2.x, h0[12]); h0[13] = fma2(xx0, s2.y, h0[13]);
                h1[12] = fma2(xx1, s2.x, h1[12]); h1[13] = fma2(xx1, s2.y, h1[13]);
                ulonglong2 c3 = wc[3];               // LDC.128 (cols 12..15)
                ulonglong2 s3 = ws[3];               // LDS.128 (cols 28..31)
                h0[6] = fma2(xx0, c3.x, h0[6]);  h0[7] = fma2(xx0, c3.y, h0[7]);
                h1[6] = fma2(xx1, c3.x, h1[6]);  h1[7] = fma2(xx1, c3.y, h1[7]);
                h0[14] = fma2(xx0, s3.x, h0[14]); h0[15] = fma2(xx0, s3.y, h0[15]);
                h1[14] = fma2(xx1, s3.x, h1[14]); h1[15] = fma2(xx1, s3.y, h1[15]);
            }
        }
    }

    float hr0[32], hr1[32];
    #pragma unroll
    for (int j = 0; j < 16; j++) {
        float a, b;
        upk2(h0[j], a, b);
        hr0[2 * j] = fmaxf(a, 0.0f); hr0[2 * j + 1] = fmaxf(b, 0.0f);
        upk2(h1[j], a, b);
        hr1[2 * j] = fmaxf(a, 0.0f); hr1[2 * j + 1] = fmaxf(b, 0.0f);
    }

    // ---- layers 2+3, sequential per edge ----
    const unsigned long long* b2p = (const unsigned long long*)cb2;
    float b3v = cb3[0];

    {
        unsigned long long g[16];
        #pragma unroll
        for (int j = 0; j < 16; j++) g[j] = b2p[j];
        #pragma unroll 4
        for (int k = 0; k < HID; k++) {
            unsigned long long xx = pk2(hr0[k], hr0[k]);
            const ulonglong2* wc = (const ulonglong2*)(cW2 + k * 32);
            const ulonglong2* ws = (const ulonglong2*)(sW2 + k * 16);
            ulonglong2 c0 = wc[0], c1 = wc[1], c2 = wc[2], c3 = wc[3];
            ulonglong2 s0 = ws[0], s1 = ws[1], s2 = ws[2], s3 = ws[3];
            g[0] = fma2(xx, c0.x, g[0]);  g[1] = fma2(xx, c0.y, g[1]);
            g[2] = fma2(xx, c1.x, g[2]);  g[3] = fma2(xx, c1.y, g[3]);
            g[4] = fma2(xx, c2.x, g[4]);  g[5] = fma2(xx, c2.y, g[5]);
            g[6] = fma2(xx, c3.x, g[6]);  g[7] = fma2(xx, c3.y, g[7]);
            g[8]  = fma2(xx, s0.x, g[8]);  g[9]  = fma2(xx, s0.y, g[9]);
            g[10] = fma2(xx, s1.x, g[10]); g[11] = fma2(xx, s1.y, g[11]);
            g[12] = fma2(xx, s2.x, g[12]); g[13] = fma2(xx, s2.y, g[13]);
            g[14] = fma2(xx, s3.x, g[14]); g[15] = fma2(xx, s3.y, g[15]);
        }
        float w = b3v;
        #pragma unroll
        for (int j = 0; j < 16; j++) {
            float a, b;
            upk2(g[j], a, b);
            w = fmaf(fmaxf(a, 0.0f), cW3[2 * j],     w);
            w = fmaf(fmaxf(b, 0.0f), cW3[2 * j + 1], w);
        }
        atomicAdd(out + row0, w * __ldg(u + col0));
    }
    {
        unsigned long long g[16];
        #pragma unroll
        for (int j = 0; j < 16; j++) g[j] = b2p[j];
        #pragma unroll 4
        for (int k = 0; k < HID; k++) {
            unsigned long long xx = pk2(hr1[k], hr1[k]);
            const ulonglong2* wc = (const ulonglong2*)(cW2 + k * 32);
            const ulonglong2* ws = (const ulonglong2*)(sW2 + k * 16);
            ulonglong2 c0 = wc[0], c1 = wc[1], c2 = wc[2], c3 = wc[3];
            ulonglong2 s0 = ws[0], s1 = ws[1], s2 = ws[2], s3 = ws[3];
            g[0] = fma2(xx, c0.x, g[0]);  g[1] = fma2(xx, c0.y, g[1]);
            g[2] = fma2(xx, c1.x, g[2]);  g[3] = fma2(xx, c1.y, g[3]);
            g[4] = fma2(xx, c2.x, g[4]);  g[5] = fma2(xx, c2.y, g[5]);
            g[6] = fma2(xx, c3.x, g[6]);  g[7] = fma2(xx, c3.y, g[7]);
            g[8]  = fma2(xx, s0.x, g[8]);  g[9]  = fma2(xx, s0.y, g[9]);
            g[10] = fma2(xx, s1.x, g[10]); g[11] = fma2(xx, s1.y, g[11]);
            g[12] = fma2(xx, s2.x, g[12]); g[13] = fma2(xx, s2.y, g[13]);
            g[14] = fma2(xx, s3.x, g[14]); g[15] = fma2(xx, s3.y, g[15]);
        }
        float w = b3v;
        #pragma unroll
        for (int j = 0; j < 16; j++) {
            float a, b;
            upk2(g[j], a, b);
            w = fmaf(fmaxf(a, 0.0f), cW3[2 * j],     w);
            w = fmaf(fmaxf(b, 0.0f), cW3[2 * j + 1], w);
        }
        if (v1) atomicAdd(out + row1, w * __ldg(u + col1));
    }
}

extern "C" void kernel_launch(void* const* d_in, const int* in_sizes, int n_in,
                              void* d_out, int out_size) {
    const float* x  = (const float*)d_in[0];
    const void*  ei = d_in[1];
    const float* u  = (const float*)d_in[2];
    const float* W1 = (const float*)d_in[3];
    const float* b1 = (const float*)d_in[4];
    const float* W2 = (const float*)d_in[5];
    const float* b2 = (const float*)d_in[6];
    const float* W3 = (const float*)d_in[7];
    const float* b3 = (const float*)d_in[8];
    float* out = (float*)d_out;

    // Full matrices into constant (D2D async: graph-capturable).
    cudaMemcpyToSymbolAsync(cW1, W1, 2 * DF * HID * sizeof(float), 0,
                            cudaMemcpyDeviceToDevice, 0);
    cudaMemcpyToSymbolAsync(cW2, W2, HID * HID * sizeof(float), 0,
                            cudaMemcpyDeviceToDevice, 0);
    cudaMemcpyToSymbolAsync(cb1, b1, HID * sizeof(float), 0,
                            cudaMemcpyDeviceToDevice, 0);
    cudaMemcpyToSymbolAsync(cb2, b2, HID * sizeof(float), 0,
                            cudaMemcpyDeviceToDevice, 0);
    cudaMemcpyToSymbolAsync(cW3, W3, HID * sizeof(float), 0,
                            cudaMemcpyDeviceToDevice, 0);
    cudaMemcpyToSymbolAsync(cb3, b3, sizeof(float), 0,
                            cudaMemcpyDeviceToDevice, 0);

    init_kernel<<<(NN + 255) / 256, 256>>>((const long long*)ei, out);
    edge_mlp_kernel<<<(NE + 511) / 512, 256>>>(
        (const float4*)x, ei, u, W1, W2, out);
}

// round 7
// speedup vs baseline: 1.9646x; 1.9646x over previous
#include <cuda_runtime.h>

#define NE 1200000
#define NN 50000
#define DF 64
#define HID 32

__device__ int g_idx_is64;

// Per-node partial products: AB[n][0..31] = x[n]@W1[0:64] + b1 (A' half),
//                            AB[n][32..63] = x[n]@W1[64:128]   (B half).
// 64 floats = 256B per node -> each half is exactly one 128B line.
__device__ __align__(256) float g_AB[NN * 64];   // 12.8 MB scratch (L2-resident)

__constant__ float cW1[2 * DF * HID];   // 16 KB
__constant__ float cW2[HID * HID];      // 4 KB
__constant__ float cb1[HID];
__constant__ float cb2[HID];
__constant__ float cW3[HID];
__constant__ float cb3[1];

// ---- packed f32x2 helpers (Blackwell sm_103a) ----
__device__ __forceinline__ unsigned long long pk2(float a, float b) {
    unsigned long long r;
    asm("mov.b64 %0, {%1, %2};" : "=l"(r) : "f"(a), "f"(b));
    return r;
}
__device__ __forceinline__ void upk2(unsigned long long v, float& a, float& b) {
    asm("mov.b64 {%0, %1}, %2;" : "=f"(a), "=f"(b) : "l"(v));
}
__device__ __forceinline__ unsigned long long fma2(unsigned long long a,
                                                   unsigned long long b,
                                                   unsigned long long c) {
    unsigned long long d;
    asm("fma.rn.f32x2 %0, %1, %2, %3;" : "=l"(d) : "l"(a), "l"(b), "l"(c));
    return d;
}
__device__ __forceinline__ unsigned long long add2(unsigned long long a,
                                                   unsigned long long b) {
    unsigned long long d;
    asm("add.rn.f32x2 %0, %1, %2;" : "=l"(d) : "l"(a), "l"(b));
    return d;
}

// Fused: zero output + detect edge_index dtype (JAX canonicalizes int64->int32
// unless x64 mode). Genuine int64 has every 8-byte value in [0, NN).
__global__ void init_kernel(const long long* __restrict__ ei,
                            float* __restrict__ out) {
    int i = blockIdx.x * blockDim.x + threadIdx.x;
    if (i < NN) out[i] = 0.0f;
    if (i == 0) {
        int ok64 = 1;
        for (int k = 0; k < 8; k++) {
            long long v = ei[k];
            if (v < 0 || v >= NN) ok64 = 0;
        }
        g_idx_is64 = ok64;
    }
}

// Pre-pass: one thread per node per half (gridDim.y = 2 selects A'/B half).
__global__ __launch_bounds__(256)
void node_gemm_kernel(const float4* __restrict__ x4) {
    int node = blockIdx.x * blockDim.x + threadIdx.x;
    if (node >= NN) return;
    int half = blockIdx.y;             // 0 -> A' (+b1), 1 -> B

    unsigned long long acc[16];        // 32 outputs as f32x2 pairs
    if (half == 0) {
        const unsigned long long* b1p = (const unsigned long long*)cb1;
        #pragma unroll
        for (int j = 0; j < 16; j++) acc[j] = b1p[j];
    } else {
        #pragma unroll
        for (int j = 0; j < 16; j++) acc[j] = 0ULL;
    }

    const float4* xp = x4 + (long)node * (DF / 4);
    #pragma unroll 4
    for (int q = 0; q < DF / 4; q++) {
        float4 xv = __ldg(xp + q);
        float vals[4] = {xv.x, xv.y, xv.z, xv.w};
        #pragma unroll
        for (int c = 0; c < 4; c++) {
            int k = half * DF + q * 4 + c;
            unsigned long long xx = pk2(vals[c], vals[c]);
            const ulonglong2* wrow = (const ulonglong2*)(cW1 + k * 32);
            #pragma unroll
            for (int m = 0; m < 8; m++) {
                ulonglong2 wv = wrow[m];
                acc[2 * m]     = fma2(xx, wv.x, acc[2 * m]);
                acc[2 * m + 1] = fma2(xx, wv.y, acc[2 * m + 1]);
            }
        }
    }

    ulonglong2* dst = (ulonglong2*)(g_AB + (long)node * 64 + half * 32);
    #pragma unroll
    for (int m = 0; m < 8; m++) {
        ulonglong2 v; v.x = acc[2 * m]; v.y = acc[2 * m + 1];
        dst[m] = v;
    }
}

// Edge kernel: h = relu(A'[row] + B[col]); g = relu(h@W2+b2); w = g@W3+b3;
// out[row] += w * u[col].
__global__ __launch_bounds__(256, 3)
void edge_mlp_kernel(const void* __restrict__ ei_raw,
                     const float* __restrict__ u,
                     float* __restrict__ out)
{
    long e = (long)blockIdx.x * blockDim.x + threadIdx.x;
    if (e >= NE) return;

    int row, col;
    if (g_idx_is64) {
        const long long* ei = (const long long*)ei_raw;
        row = (int)ei[e];
        col = (int)ei[NE + e];
    } else {
        const int* ei = (const int*)ei_raw;
        row = ei[e];
        col = ei[NE + e];
    }
    row = min(max(row, 0), NN - 1);
    col = min(max(col, 0), NN - 1);

    float uc = __ldg(u + col);

    // Gather one line per node: A'[row] (bytes 0..127), B[col] (bytes 128..255).
    const ulonglong2* ap = (const ulonglong2*)(g_AB + (long)row * 64);
    const ulonglong2* bp = (const ulonglong2*)(g_AB + (long)col * 64 + 32);

    float hr[32];
    #pragma unroll
    for (int m = 0; m < 8; m++) {
        ulonglong2 av = __ldg(ap + m);           // LDG.128
        ulonglong2 bv = __ldg(bp + m);           // LDG.128
        unsigned long long s0 = add2(av.x, bv.x);
        unsigned long long s1 = add2(av.y, bv.y);
        float a, b;
        upk2(s0, a, b);
        hr[4 * m]     = fmaxf(a, 0.0f);
        hr[4 * m + 1] = fmaxf(b, 0.0f);
        upk2(s1, a, b);
        hr[4 * m + 2] = fmaxf(a, 0.0f);
        hr[4 * m + 3] = fmaxf(b, 0.0f);
    }

    // layer 2: g = relu(hr @ W2 + b2), weights via constant port.
    unsigned long long g[16];
    const unsigned long long* b2p = (const unsigned long long*)cb2;
    #pragma unroll
    for (int j = 0; j < 16; j++) g[j] = b2p[j];

    #pragma unroll 4
    for (int k = 0; k < HID; k++) {
        unsigned long long xx = pk2(hr[k], hr[k]);
        const ulonglong2* wrow = (const ulonglong2*)(cW2 + k * 32);
        #pragma unroll
        for (int m = 0; m < 8; m++) {
            ulonglong2 wv = wrow[m];
            g[2 * m]     = fma2(xx, wv.x, g[2 * m]);
            g[2 * m + 1] = fma2(xx, wv.y, g[2 * m + 1]);
        }
    }

    // layer 3
    float w = cb3[0];
    #pragma unroll
    for (int j = 0; j < 16; j++) {
        float a, b;
        upk2(g[j], a, b);
        w = fmaf(fmaxf(a, 0.0f), cW3[2 * j],     w);
        w = fmaf(fmaxf(b, 0.0f), cW3[2 * j + 1], w);
    }

    atomicAdd(out + row, w * uc);
}

extern "C" void kernel_launch(void* const* d_in, const int* in_sizes, int n_in,
                              void* d_out, int out_size) {
    const float* x  = (const float*)d_in[0];
    const void*  ei = d_in[1];
    const float* u  = (const float*)d_in[2];
    const float* W1 = (const float*)d_in[3];
    const float* b1 = (const float*)d_in[4];
    const float* W2 = (const float*)d_in[5];
    const float* b2 = (const float*)d_in[6];
    const float* W3 = (const float*)d_in[7];
    const float* b3 = (const float*)d_in[8];
    float* out = (float*)d_out;

    cudaMemcpyToSymbolAsync(cW1, W1, 2 * DF * HID * sizeof(float), 0,
                            cudaMemcpyDeviceToDevice, 0);
    cudaMemcpyToSymbolAsync(cW2, W2, HID * HID * sizeof(float), 0,
                            cudaMemcpyDeviceToDevice, 0);
    cudaMemcpyToSymbolAsync(cb1, b1, HID * sizeof(float), 0,
                            cudaMemcpyDeviceToDevice, 0);
    cudaMemcpyToSymbolAsync(cb2, b2, HID * sizeof(float), 0,
                            cudaMemcpyDeviceToDevice, 0);
    cudaMemcpyToSymbolAsync(cW3, W3, HID * sizeof(float), 0,
                            cudaMemcpyDeviceToDevice, 0);
    cudaMemcpyToSymbolAsync(cb3, b3, sizeof(float), 0,
                            cudaMemcpyDeviceToDevice, 0);

    init_kernel<<<(NN + 255) / 256, 256>>>((const long long*)ei, out);

    dim3 gg((NN + 255) / 256, 2);
    node_gemm_kernel<<<gg, 256>>>((const float4*)x);

    edge_mlp_kernel<<<(NE + 255) / 256, 256>>>(ei, u, out);
}

// round 8
// speedup vs baseline: 2.2510x; 1.1458x over previous
#include <cuda_runtime.h>
#include <cuda_fp16.h>

#define NE 1200000
#define NN 50000
#define DF 64
#define HID 32

__device__ int g_idx_is64;

// fp16 per-node partials, one 128-byte line per node:
//   bytes [0,64)   : A'[n] = x[n]@W1[0:64] + b1   (32 fp16)
//   bytes [64,128) : B[n]  = x[n]@W1[64:128]      (32 fp16)
__device__ __align__(128) __half g_ABh[NN * 64];   // 6.4 MB (L2-resident)

__constant__ float cW1[2 * DF * HID];   // 16 KB
__constant__ float cW2[HID * HID];      // 4 KB
__constant__ float cb1[HID];
__constant__ float cb2[HID];
__constant__ float cW3[HID];
__constant__ float cb3[1];

// ---- packed f32x2 helpers (Blackwell sm_103a) ----
__device__ __forceinline__ unsigned long long pk2(float a, float b) {
    unsigned long long r;
    asm("mov.b64 %0, {%1, %2};" : "=l"(r) : "f"(a), "f"(b));
    return r;
}
__device__ __forceinline__ void upk2(unsigned long long v, float& a, float& b) {
    asm("mov.b64 {%0, %1}, %2;" : "=f"(a), "=f"(b) : "l"(v));
}
__device__ __forceinline__ unsigned long long fma2(unsigned long long a,
                                                   unsigned long long b,
                                                   unsigned long long c) {
    unsigned long long d;
    asm("fma.rn.f32x2 %0, %1, %2, %3;" : "=l"(d) : "l"(a), "l"(b), "l"(c));
    return d;
}

// Pre-pass: one thread per node per half (blockIdx.y selects A'/B).
// Fused with output zeroing and edge_index dtype probe (JAX canonicalizes
// int64->int32 unless x64 mode; genuine int64 has all values in [0, NN)).
__global__ __launch_bounds__(256)
void node_gemm_kernel(const float4* __restrict__ x4,
                      const long long* __restrict__ ei,
                      float* __restrict__ out) {
    int node = blockIdx.x * blockDim.x + threadIdx.x;
    int half = blockIdx.y;             // 0 -> A' (+b1), 1 -> B

    if (half == 0 && node < NN) out[node] = 0.0f;
    if (half == 0 && node == 0) {
        int ok64 = 1;
        for (int k = 0; k < 8; k++) {
            long long v = ei[k];
            if (v < 0 || v >= NN) ok64 = 0;
        }
        g_idx_is64 = ok64;
    }
    if (node >= NN) return;

    unsigned long long acc[16];        // 32 outputs as f32x2 pairs
    if (half == 0) {
        const unsigned long long* b1p = (const unsigned long long*)cb1;
        #pragma unroll
        for (int j = 0; j < 16; j++) acc[j] = b1p[j];
    } else {
        #pragma unroll
        for (int j = 0; j < 16; j++) acc[j] = 0ULL;
    }

    const float4* xp = x4 + (long)node * (DF / 4);
    #pragma unroll 4
    for (int q = 0; q < DF / 4; q++) {
        float4 xv = __ldg(xp + q);
        float vals[4] = {xv.x, xv.y, xv.z, xv.w};
        #pragma unroll
        for (int c = 0; c < 4; c++) {
            int k = half * DF + q * 4 + c;
            unsigned long long xx = pk2(vals[c], vals[c]);
            const ulonglong2* wrow = (const ulonglong2*)(cW1 + k * 32);
            #pragma unroll
            for (int m = 0; m < 8; m++) {
                ulonglong2 wv = wrow[m];
                acc[2 * m]     = fma2(xx, wv.x, acc[2 * m]);
                acc[2 * m + 1] = fma2(xx, wv.y, acc[2 * m + 1]);
            }
        }
    }

    // fp32 -> fp16 pack: hv[j] holds output cols (2j, 2j+1)
    __half2 hv[16];
    #pragma unroll
    for (int j = 0; j < 16; j++) {
        float a, b;
        upk2(acc[j], a, b);
        hv[j] = __floats2half2_rn(a, b);
    }
    uint4* dst = (uint4*)((char*)g_ABh + (long)node * 128 + half * 64);
    const uint4* src = (const uint4*)hv;
    #pragma unroll
    for (int m = 0; m < 4; m++) dst[m] = src[m];
}

// Edge kernel: h = relu(A'[row] + B[col]); g = relu(h@W2+b2); w = g@W3+b3;
// out[row] += w * u[col].
__global__ __launch_bounds__(256, 3)
void edge_mlp_kernel(const void* __restrict__ ei_raw,
                     const float* __restrict__ u,
                     float* __restrict__ out)
{
    long e = (long)blockIdx.x * blockDim.x + threadIdx.x;
    if (e >= NE) return;

    int row, col;
    if (g_idx_is64) {
        const long long* ei = (const long long*)ei_raw;
        row = (int)ei[e];
        col = (int)ei[NE + e];
    } else {
        const int* ei = (const int*)ei_raw;
        row = ei[e];
        col = ei[NE + e];
    }
    row = min(max(row, 0), NN - 1);
    col = min(max(col, 0), NN - 1);

    float uc = __ldg(u + col);

    const uint4* ap = (const uint4*)((const char*)g_ABh + (long)row * 128);
    const uint4* bp = (const uint4*)((const char*)g_ABh + (long)col * 128 + 64);

    float hr[32];
    #pragma unroll
    for (int m = 0; m < 4; m++) {
        uint4 av = __ldg(ap + m);                 // 8 fp16 of A'
        uint4 bv = __ldg(bp + m);                 // 8 fp16 of B
        const __half2* ah = (const __half2*)&av;
        const __half2* bh = (const __half2*)&bv;
        #pragma unroll
        for (int p = 0; p < 4; p++) {
            float2 fa = __half22float2(ah[p]);
            float2 fb = __half22float2(bh[p]);
            hr[m * 8 + 2 * p]     = fmaxf(fa.x + fb.x, 0.0f);
            hr[m * 8 + 2 * p + 1] = fmaxf(fa.y + fb.y, 0.0f);
        }
    }

    // layer 2: g = relu(hr @ W2 + b2), weights via constant port.
    unsigned long long g[16];
    const unsigned long long* b2p = (const unsigned long long*)cb2;
    #pragma unroll
    for (int j = 0; j < 16; j++) g[j] = b2p[j];

    #pragma unroll 4
    for (int k = 0; k < HID; k++) {
        unsigned long long xx = pk2(hr[k], hr[k]);
        const ulonglong2* wrow = (const ulonglong2*)(cW2 + k * 32);
        #pragma unroll
        for (int m = 0; m < 8; m++) {
            ulonglong2 wv = wrow[m];
            g[2 * m]     = fma2(xx, wv.x, g[2 * m]);
            g[2 * m + 1] = fma2(xx, wv.y, g[2 * m + 1]);
        }
    }

    // layer 3
    float w = cb3[0];
    #pragma unroll
    for (int j = 0; j < 16; j++) {
        float a, b;
        upk2(g[j], a, b);
        w = fmaf(fmaxf(a, 0.0f), cW3[2 * j],     w);
        w = fmaf(fmaxf(b, 0.0f), cW3[2 * j + 1], w);
    }

    atomicAdd(out + row, w * uc);
}

extern "C" void kernel_launch(void* const* d_in, const int* in_sizes, int n_in,
                              void* d_out, int out_size) {
    const float* x  = (const float*)d_in[0];
    const void*  ei = d_in[1];
    const float* u  = (const float*)d_in[2];
    const float* W1 = (const float*)d_in[3];
    const float* b1 = (const float*)d_in[4];
    const float* W2 = (const float*)d_in[5];
    const float* b2 = (const float*)d_in[6];
    const float* W3 = (const float*)d_in[7];
    const float* b3 = (const float*)d_in[8];
    float* out = (float*)d_out;

    cudaMemcpyToSymbolAsync(cW1, W1, 2 * DF * HID * sizeof(float), 0,
                            cudaMemcpyDeviceToDevice, 0);
    cudaMemcpyToSymbolAsync(cW2, W2, HID * HID * sizeof(float), 0,
                            cudaMemcpyDeviceToDevice, 0);
    cudaMemcpyToSymbolAsync(cb1, b1, HID * sizeof(float), 0,
                            cudaMemcpyDeviceToDevice, 0);
    cudaMemcpyToSymbolAsync(cb2, b2, HID * sizeof(float), 0,
                            cudaMemcpyDeviceToDevice, 0);
    cudaMemcpyToSymbolAsync(cW3, W3, HID * sizeof(float), 0,
                            cudaMemcpyDeviceToDevice, 0);
    cudaMemcpyToSymbolAsync(cb3, b3, sizeof(float), 0,
                            cudaMemcpyDeviceToDevice, 0);

    dim3 gg((NN + 255) / 256, 2);
    node_gemm_kernel<<<gg, 256>>>((const float4*)x, (const long long*)ei, out);

    edge_mlp_kernel<<<(NE + 255) / 256, 256>>>(ei, u, out);
}